// round 7
// baseline (speedup 1.0000x reference)
#include <cuda_runtime.h>
#include <cstdint>

#define NUM_CLASSES 100000
#define FEAT_DIM    128
#define BATCH       16384
#define LOSS_WEIGHT 0.01f
#define TOTAL       (NUM_CLASSES * FEAT_DIM)      // 12,800,000

#define K4_WARPS   8                              // scatter warps per block
#define K4_SPW     4                              // samples per warp
#define K4_THREADS (K4_WARPS * 32)
#define SCATTER_BLOCKS (BATCH / (K4_WARPS * K4_SPW))   // 512

// Shifted float4 vectors: elements [3 .. 3+4*NV) are 16B-aligned in grad
// (grad = out+1 is 4B-aligned; byte of element e is 4+4e; 16B-aligned iff
// e ≡ 3 mod 4).
#define K3_NV ((TOTAL - 3) / 4)                   // 3,199,999
#define ZERO_THREADS 256
#define ZERO_BLOCKS  ((K3_NV + 1 + ZERO_THREADS - 1) / ZERO_THREADS)  // 12500

// Scratch (static device globals — no allocation).
__device__ float g_counts[NUM_CLASSES];           // 16B-aligned
__device__ int   g_y_is64;   // 1 if labels are int64, 0 if int32

__device__ __forceinline__ int get_label(const void* __restrict__ y, int i) {
    if (g_y_is64) return (int)((const long long*)y)[i];
    return ((const int*)y)[i];
}

// ---------------------------------------------------------------------------
// K1: zero counts (float4) + loss; block 0 probes the label dtype.
// ---------------------------------------------------------------------------
__global__ void k_zero(const int* __restrict__ y_words,
                       float* __restrict__ loss_out) {
    int i = blockIdx.x * blockDim.x + threadIdx.x;
    if (i < NUM_CLASSES / 4) {
        reinterpret_cast<float4*>(g_counts)[i] =
            make_float4(0.f, 0.f, 0.f, 0.f);
    }
    if (i == 0) *loss_out = 0.0f;

    if (blockIdx.x == 0) {
        int t = threadIdx.x;                       // 0..255
        unsigned nz = (y_words[2 * t + 1] != 0) ? 1u : 0u;
        nz = __ballot_sync(0xFFFFFFFFu, nz != 0);
        __shared__ unsigned s_nz[8];
        if ((t & 31) == 0) s_nz[t >> 5] = nz;
        __syncthreads();
        if (t == 0) {
            unsigned any = 0;
            #pragma unroll
            for (int w = 0; w < 8; w++) any |= s_nz[w];
            g_y_is64 = (any == 0) ? 1 : 0;
        }
    }
}

// ---------------------------------------------------------------------------
// K2: histogram of labels
// ---------------------------------------------------------------------------
__global__ void k_count(const void* __restrict__ y) {
    int i = blockIdx.x * blockDim.x + threadIdx.x;
    if (i < BATCH) {
        atomicAdd(&g_counts[get_label(y, i)], 1.0f);
    }
}

// ---------------------------------------------------------------------------
// K2.5: initialize HIT rows only: grad[c,:] = ratio_c * centers[c,:].
// ~15% of rows. Must complete before the scatter REDs. Empty rows untouched.
// Boundary vectors (1/32): first element in row cA, last three in row cA+1.
// ---------------------------------------------------------------------------
__global__ void k_init_hit(const float* __restrict__ centers,
                           float* __restrict__ grad) {
    int j = blockIdx.x * blockDim.x + threadIdx.x;
    if (j < K3_NV) {
        int e0 = 4 * j + 3;
        int cA = e0 >> 7;
        int cB = (e0 + 3) >> 7;
        if (cA == cB) {
            float cnt = g_counts[cA];
            if (cnt > 0.0f) {
                float r = cnt / (1.0f + cnt);
                float4 o;
                o.x = r * __ldg(centers + e0);
                o.y = r * __ldg(centers + e0 + 1);
                o.z = r * __ldg(centers + e0 + 2);
                o.w = r * __ldg(centers + e0 + 3);
                *reinterpret_cast<float4*>(grad + e0) = o;
            }
        } else {
            float cntA = g_counts[cA], cntB = g_counts[cB];
            if (cntA > 0.0f)
                grad[e0] = (cntA / (1.0f + cntA)) * centers[e0];
            if (cntB > 0.0f) {
                float r = cntB / (1.0f + cntB);
                grad[e0 + 1] = r * centers[e0 + 1];
                grad[e0 + 2] = r * centers[e0 + 2];
                grad[e0 + 3] = r * centers[e0 + 3];
            }
        }
    } else if (j == K3_NV) {
        float cnt0 = g_counts[0];
        if (cnt0 > 0.0f) {
            float r = cnt0 / (1.0f + cnt0);
            grad[0] = r * centers[0];
            grad[1] = r * centers[1];
            grad[2] = r * centers[2];
        }
        float cntL = g_counts[NUM_CLASSES - 1];
        if (cntL > 0.0f)
            grad[TOTAL - 1] = (cntL / (1.0f + cntL)) * centers[TOTAL - 1];
    }
}

// ---------------------------------------------------------------------------
// K34 (merged): blockIdx < SCATTER_BLOCKS -> scatter + fused loss;
// remaining blocks -> zero the EMPTY grad rows (disjoint from hit rows,
// so no ordering needed vs the concurrent REDs). Overlaps the 43MB
// zero-store DRAM stream with the latency-bound scatter.
// ---------------------------------------------------------------------------
__global__ void __launch_bounds__(K4_THREADS)
k_merged(const void* __restrict__ y,
         const float* __restrict__ feat,
         const float* __restrict__ centers,
         float* __restrict__ grad,
         float* __restrict__ loss_out) {
    if (blockIdx.x >= SCATTER_BLOCKS) {
        // ---- zero path: empty rows only (streaming stores) ----
        int j = (blockIdx.x - SCATTER_BLOCKS) * ZERO_THREADS + threadIdx.x;
        if (j < K3_NV) {
            int e0 = 4 * j + 3;
            int cA = e0 >> 7;
            int cB = (e0 + 3) >> 7;
            if (cA == cB) {
                if (g_counts[cA] == 0.0f) {
                    __stcs(reinterpret_cast<float4*>(grad + e0),
                           make_float4(0.f, 0.f, 0.f, 0.f));
                }
            } else {
                if (g_counts[cA] == 0.0f) grad[e0] = 0.0f;
                if (g_counts[cB] == 0.0f) {
                    grad[e0 + 1] = 0.0f;
                    grad[e0 + 2] = 0.0f;
                    grad[e0 + 3] = 0.0f;
                }
            }
        } else if (j == K3_NV) {
            if (g_counts[0] == 0.0f) {
                grad[0] = 0.0f; grad[1] = 0.0f; grad[2] = 0.0f;
            }
            if (g_counts[NUM_CLASSES - 1] == 0.0f)
                grad[TOTAL - 1] = 0.0f;
        }
        return;
    }

    // ---- scatter path ----
    int wid  = threadIdx.x >> 5;
    int lane = threadIdx.x & 31;
    int base = (blockIdx.x * K4_WARPS + wid) * K4_SPW;

    int c[K4_SPW];
    if (!g_y_is64) {
        int4 L = reinterpret_cast<const int4*>((const int*)y + base)[0];
        c[0] = L.x; c[1] = L.y; c[2] = L.z; c[3] = L.w;
    } else {
        const longlong2* y2 = reinterpret_cast<const longlong2*>(y);
        longlong2 a = y2[base / 2], b = y2[base / 2 + 1];
        c[0] = (int)a.x; c[1] = (int)a.y; c[2] = (int)b.x; c[3] = (int)b.y;
    }

    float inv[K4_SPW];
    const float* frow[K4_SPW];
    const float* crow[K4_SPW];
    #pragma unroll
    for (int s = 0; s < K4_SPW; s++) {
        inv[s]  = 1.0f / (1.0f + g_counts[c[s]]);
        frow[s] = feat + (base + s) * FEAT_DIM;
        crow[s] = centers + c[s] * FEAT_DIM;
    }

    // Front-batch all 32 loads for maximum MLP.
    float f[K4_SPW][4], e[K4_SPW][4];
    #pragma unroll
    for (int s = 0; s < K4_SPW; s++)
        #pragma unroll
        for (int k = 0; k < 4; k++)
            f[s][k] = frow[s][lane + 32 * k];
    #pragma unroll
    for (int s = 0; s < K4_SPW; s++)
        #pragma unroll
        for (int k = 0; k < 4; k++)
            e[s][k] = crow[s][lane + 32 * k];

    #pragma unroll
    for (int s = 0; s < K4_SPW; s++) {
        float* grow = grad + c[s] * FEAT_DIM;
        #pragma unroll
        for (int k = 0; k < 4; k++) {
            asm volatile("red.global.add.f32 [%0], %1;"
                         :: "l"(grow + lane + 32 * k),
                            "f"(-f[s][k] * inv[s]) : "memory");
        }
    }

    float v = 0.0f;
    #pragma unroll
    for (int s = 0; s < K4_SPW; s++)
        #pragma unroll
        for (int k = 0; k < 4; k++) {
            float d = f[s][k] - e[s][k];
            v += d * d;
        }

    #pragma unroll
    for (int o = 16; o > 0; o >>= 1)
        v += __shfl_down_sync(0xFFFFFFFFu, v, o);

    __shared__ float s_part[K4_WARPS];
    if (lane == 0) s_part[wid] = v;
    __syncthreads();
    if (threadIdx.x == 0) {
        float t = 0.0f;
        #pragma unroll
        for (int w = 0; w < K4_WARPS; w++) t += s_part[w];
        t *= LOSS_WEIGHT * 0.5f;
        asm volatile("red.global.add.f32 [%0], %1;"
                     :: "l"(loss_out), "f"(t) : "memory");
    }
}

// ---------------------------------------------------------------------------
extern "C" void kernel_launch(void* const* d_in, const int* in_sizes, int n_in,
                              void* d_out, int out_size) {
    const void*  y       = d_in[0];
    const float* feat    = (const float*)d_in[1];
    const float* centers = (const float*)d_in[2];

    float* out      = (float*)d_out;
    float* loss_out = out;          // output 0: scalar loss
    float* grad     = out + 1;      // output 1: [C, D] grad (4B-aligned only!)

    // K1: zero counts + loss, detect label dtype
    {
        int threads = 256;
        int blocks  = (NUM_CLASSES / 4 + threads - 1) / threads;  // 98
        k_zero<<<blocks, threads>>>((const int*)y, loss_out);
    }
    // K2: histogram
    {
        int threads = 256;
        int blocks  = (BATCH + threads - 1) / threads;
        k_count<<<blocks, threads>>>(y);
    }
    // K2.5: hit rows = ratio * centers (must precede scatter REDs)
    {
        k_init_hit<<<ZERO_BLOCKS, ZERO_THREADS>>>(centers, grad);
    }
    // K34: scatter + loss (blocks [0,512)) || zero empty rows (rest)
    {
        k_merged<<<SCATTER_BLOCKS + ZERO_BLOCKS, K4_THREADS>>>(
            y, feat, centers, grad, loss_out);
    }
}

// round 8
// speedup vs baseline: 1.0854x; 1.0854x over previous
#include <cuda_runtime.h>
#include <cstdint>

#define NUM_CLASSES 100000
#define FEAT_DIM    128
#define BATCH       16384
#define LOSS_WEIGHT 0.01f
#define TOTAL       (NUM_CLASSES * FEAT_DIM)      // 12,800,000

#define K4_WARPS   8
#define K4_SPW     4
#define K4_THREADS (K4_WARPS * 32)
#define SCATTER_BLOCKS (BATCH / (K4_WARPS * K4_SPW))   // 512

// Shifted float4 vectors over grad (= out+1, 4B-aligned): element e is
// 16B-aligned iff e ≡ 3 (mod 4). Vectors cover [3, 3+4*K3_NV).
#define K3_NV ((TOTAL - 3) / 4)                   // 3,199,999
#define ZERO_THREADS 256
#define ZERO_BLOCKS  ((K3_NV + 1 + ZERO_THREADS - 1) / ZERO_THREADS)  // 12500

// Scratch (static device globals — zero-initialized at load; every call
// restores the zero-invariant on whatever it touched).
__device__ float g_counts[NUM_CLASSES];
__device__ int   g_y_is64;
// featsum phase-matched to grad: use raw+1 so &featsum[e] is 16B-aligned
// exactly when &grad[e] is (e ≡ 3 mod 4).
__device__ __align__(16) float g_featsum_raw[TOTAL + 4];

__device__ __forceinline__ int get_label(const void* __restrict__ y, int i) {
    if (g_y_is64) return (int)((const long long*)y)[i];
    return ((const int*)y)[i];
}

// ---------------------------------------------------------------------------
// K1: zero counts + loss; probe label dtype (int64 -> odd words all zero).
// ---------------------------------------------------------------------------
__global__ void k_zero(const int* __restrict__ y_words,
                       float* __restrict__ loss_out) {
    int i = blockIdx.x * blockDim.x + threadIdx.x;
    if (i < NUM_CLASSES / 4) {
        reinterpret_cast<float4*>(g_counts)[i] =
            make_float4(0.f, 0.f, 0.f, 0.f);
    }
    if (i == 0) *loss_out = 0.0f;

    if (blockIdx.x == 0) {
        int t = threadIdx.x;
        unsigned nz = (y_words[2 * t + 1] != 0) ? 1u : 0u;
        nz = __ballot_sync(0xFFFFFFFFu, nz != 0);
        __shared__ unsigned s_nz[8];
        if ((t & 31) == 0) s_nz[t >> 5] = nz;
        __syncthreads();
        if (t == 0) {
            unsigned any = 0;
            #pragma unroll
            for (int w = 0; w < 8; w++) any |= s_nz[w];
            g_y_is64 = (any == 0) ? 1 : 0;
        }
    }
}

// ---------------------------------------------------------------------------
// K_main: blocks [0,512): histogram + featsum scatter + fused loss.
//         blocks [512, 13012): branch-free zero-fill of ALL grad elements
//         (streaming float4, no counts dependency — overlaps the scatter).
// No conflicts: scatter writes g_counts/g_featsum/loss; zerofill writes grad.
// ---------------------------------------------------------------------------
__global__ void __launch_bounds__(K4_THREADS)
k_main(const void* __restrict__ y,
       const float* __restrict__ feat,
       const float* __restrict__ centers,
       float* __restrict__ grad,
       float* __restrict__ loss_out) {
    if (blockIdx.x >= SCATTER_BLOCKS) {
        // ---- zero-fill path: pure streaming stores ----
        int j = (blockIdx.x - SCATTER_BLOCKS) * ZERO_THREADS + threadIdx.x;
        if (j < K3_NV) {
            __stcs(reinterpret_cast<float4*>(grad + 4 * j + 3),
                   make_float4(0.f, 0.f, 0.f, 0.f));
        } else if (j == K3_NV) {
            grad[0] = 0.0f; grad[1] = 0.0f; grad[2] = 0.0f;
            grad[TOTAL - 1] = 0.0f;
        }
        return;
    }

    // ---- scatter path: hist + featsum + loss ----
    float* featsum = g_featsum_raw + 1;
    int wid  = threadIdx.x >> 5;
    int lane = threadIdx.x & 31;
    int base = (blockIdx.x * K4_WARPS + wid) * K4_SPW;

    int c[K4_SPW];
    if (!g_y_is64) {
        int4 L = reinterpret_cast<const int4*>((const int*)y + base)[0];
        c[0] = L.x; c[1] = L.y; c[2] = L.z; c[3] = L.w;
    } else {
        const longlong2* y2 = reinterpret_cast<const longlong2*>(y);
        longlong2 a = y2[base / 2], b = y2[base / 2 + 1];
        c[0] = (int)a.x; c[1] = (int)a.y; c[2] = (int)b.x; c[3] = (int)b.y;
    }

    // histogram: one lane per sample
    if (lane < K4_SPW)
        atomicAdd(&g_counts[c[lane]], 1.0f);

    const float* frow[K4_SPW];
    const float* crow[K4_SPW];
    #pragma unroll
    for (int s = 0; s < K4_SPW; s++) {
        frow[s] = feat + (base + s) * FEAT_DIM;
        crow[s] = centers + c[s] * FEAT_DIM;
    }

    // Front-batch all 32 loads.
    float f[K4_SPW][4], e[K4_SPW][4];
    #pragma unroll
    for (int s = 0; s < K4_SPW; s++)
        #pragma unroll
        for (int k = 0; k < 4; k++)
            f[s][k] = frow[s][lane + 32 * k];
    #pragma unroll
    for (int s = 0; s < K4_SPW; s++)
        #pragma unroll
        for (int k = 0; k < 4; k++)
            e[s][k] = crow[s][lane + 32 * k];

    // featsum[c,:] += feat[i,:]  (raw sums; inv applied in k_hit)
    #pragma unroll
    for (int s = 0; s < K4_SPW; s++) {
        float* srow = featsum + c[s] * FEAT_DIM;
        #pragma unroll
        for (int k = 0; k < 4; k++) {
            asm volatile("red.global.add.f32 [%0], %1;"
                         :: "l"(srow + lane + 32 * k),
                            "f"(f[s][k]) : "memory");
        }
    }

    float v = 0.0f;
    #pragma unroll
    for (int s = 0; s < K4_SPW; s++)
        #pragma unroll
        for (int k = 0; k < 4; k++) {
            float d = f[s][k] - e[s][k];
            v += d * d;
        }

    #pragma unroll
    for (int o = 16; o > 0; o >>= 1)
        v += __shfl_down_sync(0xFFFFFFFFu, v, o);

    __shared__ float s_part[K4_WARPS];
    if (lane == 0) s_part[wid] = v;
    __syncthreads();
    if (threadIdx.x == 0) {
        float t = 0.0f;
        #pragma unroll
        for (int w = 0; w < K4_WARPS; w++) t += s_part[w];
        t *= LOSS_WEIGHT * 0.5f;
        asm volatile("red.global.add.f32 [%0], %1;"
                     :: "l"(loss_out), "f"(t) : "memory");
    }
}

// ---------------------------------------------------------------------------
// K_hit: overwrite HIT rows: grad = ratio*centers - featsum/(1+cnt);
// reset featsum to zero there (maintains the zero-invariant for the next
// call). Empty rows: nothing (zero-fill already wrote them).
// ---------------------------------------------------------------------------
__global__ void k_hit(const float* __restrict__ centers,
                      float* __restrict__ grad) {
    float* featsum = g_featsum_raw + 1;
    int j = blockIdx.x * blockDim.x + threadIdx.x;
    if (j < K3_NV) {
        int e0 = 4 * j + 3;
        int cA = e0 >> 7;
        int cB = (e0 + 3) >> 7;
        if (cA == cB) {
            float cnt = g_counts[cA];
            if (cnt > 0.0f) {
                float inv = 1.0f / (1.0f + cnt);
                float r = cnt * inv;
                float4 fs = *reinterpret_cast<float4*>(featsum + e0);
                float4 o;
                o.x = r * __ldg(centers + e0)     - fs.x * inv;
                o.y = r * __ldg(centers + e0 + 1) - fs.y * inv;
                o.z = r * __ldg(centers + e0 + 2) - fs.z * inv;
                o.w = r * __ldg(centers + e0 + 3) - fs.w * inv;
                *reinterpret_cast<float4*>(grad + e0) = o;
                *reinterpret_cast<float4*>(featsum + e0) =
                    make_float4(0.f, 0.f, 0.f, 0.f);
            }
        } else {
            float cntA = g_counts[cA], cntB = g_counts[cB];
            if (cntA > 0.0f) {
                float inv = 1.0f / (1.0f + cntA);
                grad[e0] = cntA * inv * centers[e0] - featsum[e0] * inv;
                featsum[e0] = 0.0f;
            }
            if (cntB > 0.0f) {
                float inv = 1.0f / (1.0f + cntB);
                float r = cntB * inv;
                #pragma unroll
                for (int k = 1; k < 4; k++) {
                    grad[e0 + k] = r * centers[e0 + k] - featsum[e0 + k] * inv;
                    featsum[e0 + k] = 0.0f;
                }
            }
        }
    } else if (j == K3_NV) {
        float cnt0 = g_counts[0];
        if (cnt0 > 0.0f) {
            float inv = 1.0f / (1.0f + cnt0);
            float r = cnt0 * inv;
            #pragma unroll
            for (int k = 0; k < 3; k++) {
                grad[k] = r * centers[k] - featsum[k] * inv;
                featsum[k] = 0.0f;
            }
        }
        float cntL = g_counts[NUM_CLASSES - 1];
        if (cntL > 0.0f) {
            float inv = 1.0f / (1.0f + cntL);
            grad[TOTAL - 1] = cntL * inv * centers[TOTAL - 1]
                              - featsum[TOTAL - 1] * inv;
            featsum[TOTAL - 1] = 0.0f;
        }
    }
}

// ---------------------------------------------------------------------------
extern "C" void kernel_launch(void* const* d_in, const int* in_sizes, int n_in,
                              void* d_out, int out_size) {
    const void*  y       = d_in[0];
    const float* feat    = (const float*)d_in[1];
    const float* centers = (const float*)d_in[2];

    float* out      = (float*)d_out;
    float* loss_out = out;          // output 0: scalar loss
    float* grad     = out + 1;      // output 1: [C, D] grad (4B-aligned only!)

    // K1: zero counts + loss, detect label dtype
    {
        int threads = 256;
        int blocks  = (NUM_CLASSES / 4 + threads - 1) / threads;  // 98
        k_zero<<<blocks, threads>>>((const int*)y, loss_out);
    }
    // K_main: hist + featsum scatter + loss (512 blocks) || zero-fill grad
    {
        k_main<<<SCATTER_BLOCKS + ZERO_BLOCKS, K4_THREADS>>>(
            y, feat, centers, grad, loss_out);
    }
    // K_hit: finalize hit rows, reset featsum
    {
        k_hit<<<ZERO_BLOCKS, ZERO_THREADS>>>(centers, grad);
    }
}

// round 10
// speedup vs baseline: 1.4455x; 1.3318x over previous
#include <cuda_runtime.h>
#include <cstdint>

#define NUM_CLASSES 100000
#define FEAT_DIM    128
#define BATCH       16384
#define LOSS_WEIGHT 0.01f
#define TOTAL       (NUM_CLASSES * FEAT_DIM)      // 12,800,000

#define K4_WARPS   8
#define K4_SPW     4
#define SPB        (K4_WARPS * K4_SPW)            // 32 samples per block
#define K4_THREADS (K4_WARPS * 32)
#define SCATTER_BLOCKS (BATCH / SPB)              // 512

// Zerofill: shifted float4 vectors over grad (= out+1, 4B-aligned):
// element e is 16B-aligned iff e ≡ 3 (mod 4); vectors cover [3, 3+4*K3_NV).
#define K3_NV ((TOTAL - 3) / 4)                   // 3,199,999
#define ZF_VPT 4                                  // float4 per thread
#define ZF_VPB (256 * ZF_VPT)                     // 1024 vectors per block
#define ZF_BLOCKS ((K3_NV + 1 + ZF_VPB - 1) / ZF_VPB)   // 3126

// Static scratch — zero-initialized at load; every call restores the
// zero-invariant on exactly what it touched (graph-replay safe).
__device__ float g_counts[NUM_CLASSES];
__device__ __align__(16) float g_featsum[TOTAL];  // raw per-class feat sums
__device__ int   g_hitlist[BATCH];                // c+1 per hit class; 0=empty
__device__ int   g_nhit;                          // append cursor
__device__ float g_loss;                          // loss accumulator

// ---------------------------------------------------------------------------
// K_main:
//   blocks [0, 512):   histogram (+first-toucher worklist) + featsum scatter
//                      + loss partial (RED into g_loss)
//   blocks [512, ...): branch-free zero-fill of grad (streaming float4)
// Disjoint writes: scatter -> counts/featsum/hitlist/g_loss; zerofill -> grad.
// ---------------------------------------------------------------------------
__global__ void __launch_bounds__(K4_THREADS)
k_main(const void* __restrict__ y,
       const float* __restrict__ feat,
       const float* __restrict__ centers,
       float* __restrict__ grad) {
    if (blockIdx.x >= SCATTER_BLOCKS) {
        // ---- zero-fill path: contiguous streaming stores ----
        int vbase = (blockIdx.x - SCATTER_BLOCKS) * ZF_VPB;
        const float4 z = make_float4(0.f, 0.f, 0.f, 0.f);
        #pragma unroll
        for (int k = 0; k < ZF_VPT; k++) {
            int j = vbase + k * 256 + threadIdx.x;
            if (j < K3_NV)
                __stcs(reinterpret_cast<float4*>(grad + 4 * j + 3), z);
        }
        if (vbase + threadIdx.x == K3_NV) {   // head (elems 0..2) + tail
            grad[0] = 0.0f; grad[1] = 0.0f; grad[2] = 0.0f;
            grad[TOTAL - 1] = 0.0f;
        }
        return;
    }

    // ---- scatter path ----
    int wid  = threadIdx.x >> 5;
    int lane = threadIdx.x & 31;
    int base = blockIdx.x * SPB + wid * K4_SPW;

    // Label dtype probe — FIXED RANGE: odd 32-bit words of the FIRST 32
    // int64-slots (indices 1..63), in-bounds for both dtypes (>=256B buffer)
    // and identical for every block (L2-hot). int64 labels (<2^31) -> all
    // zero; int32 -> these are labels y[1],y[3],...,y[63], P(all zero)~1e-160.
    __shared__ int s_is64;
    if (threadIdx.x < 32) {
        int odd = ((const int*)y)[2 * threadIdx.x + 1];
        unsigned b = __ballot_sync(0xFFFFFFFFu, odd != 0);
        if (threadIdx.x == 0) s_is64 = (b == 0u) ? 1 : 0;
    }
    __syncthreads();
    int is64 = s_is64;

    int c[K4_SPW];
    if (!is64) {
        int4 L = reinterpret_cast<const int4*>((const int*)y + base)[0];
        c[0] = L.x; c[1] = L.y; c[2] = L.z; c[3] = L.w;
    } else {
        const longlong2* y2 = reinterpret_cast<const longlong2*>(y);
        longlong2 a = y2[base / 2], b = y2[base / 2 + 1];
        c[0] = (int)a.x; c[1] = (int)a.y; c[2] = (int)b.x; c[3] = (int)b.y;
    }

    // histogram + first-toucher worklist (one lane per sample)
    if (lane < K4_SPW) {
        float old = atomicAdd(&g_counts[c[lane]], 1.0f);
        if (old == 0.0f) {
            int pos = atomicAdd(&g_nhit, 1);
            g_hitlist[pos] = c[lane] + 1;
        }
    }

    // Front-batch all 8 float4 loads (feat + centers rows).
    float4 f4[K4_SPW], e4[K4_SPW];
    #pragma unroll
    for (int s = 0; s < K4_SPW; s++)
        f4[s] = reinterpret_cast<const float4*>(feat + (base + s) * FEAT_DIM)[lane];
    #pragma unroll
    for (int s = 0; s < K4_SPW; s++)
        e4[s] = reinterpret_cast<const float4*>(centers + c[s] * FEAT_DIM)[lane];

    // featsum[c,:] += feat[i,:]  (vector RED, aligned scratch)
    #pragma unroll
    for (int s = 0; s < K4_SPW; s++) {
        float* dst = g_featsum + c[s] * FEAT_DIM + lane * 4;
        asm volatile("red.global.add.v4.f32 [%0], {%1, %2, %3, %4};"
                     :: "l"(dst), "f"(f4[s].x), "f"(f4[s].y),
                        "f"(f4[s].z), "f"(f4[s].w) : "memory");
    }

    float v = 0.0f;
    #pragma unroll
    for (int s = 0; s < K4_SPW; s++) {
        float d;
        d = f4[s].x - e4[s].x; v += d * d;
        d = f4[s].y - e4[s].y; v += d * d;
        d = f4[s].z - e4[s].z; v += d * d;
        d = f4[s].w - e4[s].w; v += d * d;
    }

    #pragma unroll
    for (int o = 16; o > 0; o >>= 1)
        v += __shfl_down_sync(0xFFFFFFFFu, v, o);

    __shared__ float s_part[K4_WARPS];
    if (lane == 0) s_part[wid] = v;
    __syncthreads();
    if (threadIdx.x == 0) {
        float t = 0.0f;
        #pragma unroll
        for (int w = 0; w < K4_WARPS; w++) t += s_part[w];
        asm volatile("red.global.add.f32 [%0], %1;"
                     :: "l"(&g_loss), "f"(t) : "memory");
    }
}

// ---------------------------------------------------------------------------
// K_hit: one warp per hit-list slot (<=16384 slots, ~15.1k used).
//   grad[c,:] = ratio*centers[c,:] - featsum[c,:]/(1+cnt)
// then self-reset featsum row, counts[c], hitlist slot (zero-invariant).
// Block 0 thread 0 additionally finalizes the loss and resets g_loss/g_nhit.
// ---------------------------------------------------------------------------
__global__ void __launch_bounds__(256)
k_hit(const float* __restrict__ centers,
      float* __restrict__ grad,
      float* __restrict__ loss_out) {
    if (blockIdx.x == 0 && threadIdx.x == 0) {
        *loss_out = LOSS_WEIGHT * 0.5f * g_loss;
        g_loss = 0.0f;
        g_nhit = 0;          // nobody in this kernel reads g_nhit
    }

    int slot = blockIdx.x * 8 + (threadIdx.x >> 5);
    int lane = threadIdx.x & 31;
    if (slot >= BATCH) return;

    int e = g_hitlist[slot];
    if (e == 0) return;
    int c = e - 1;

    float cnt = g_counts[c];
    float inv = 1.0f / (1.0f + cnt);
    float r   = cnt * inv;

    float4* fsrow = reinterpret_cast<float4*>(g_featsum + c * FEAT_DIM);
    const float4* cerow =
        reinterpret_cast<const float4*>(centers + c * FEAT_DIM);

    float4 fs = fsrow[lane];
    float4 ce = cerow[lane];

    float* g = grad + c * FEAT_DIM + lane * 4;
    g[0] = r * ce.x - inv * fs.x;
    g[1] = r * ce.y - inv * fs.y;
    g[2] = r * ce.z - inv * fs.z;
    g[3] = r * ce.w - inv * fs.w;

    // restore zero-invariant
    fsrow[lane] = make_float4(0.f, 0.f, 0.f, 0.f);
    if (lane == 0) {
        g_counts[c] = 0.0f;
        g_hitlist[slot] = 0;
    }
}

// ---------------------------------------------------------------------------
extern "C" void kernel_launch(void* const* d_in, const int* in_sizes, int n_in,
                              void* d_out, int out_size) {
    const void*  y       = d_in[0];
    const float* feat    = (const float*)d_in[1];
    const float* centers = (const float*)d_in[2];

    float* out      = (float*)d_out;
    float* loss_out = out;          // output 0: scalar loss
    float* grad     = out + 1;      // output 1: [C, D] grad (4B-aligned only!)

    // K_main: scatter (512 blocks) || zero-fill grad (3126 blocks)
    k_main<<<SCATTER_BLOCKS + ZF_BLOCKS, K4_THREADS>>>(y, feat, centers, grad);

    // K_hit: finalize hit rows (1 warp/slot) + loss; self-reset scratch
    k_hit<<<(BATCH + 7) / 8, 256>>>(centers, grad, loss_out);
}